// round 7
// baseline (speedup 1.0000x reference)
#include <cuda_runtime.h>
#include <math.h>

#define BATCH   256
#define LATENT  64
#define HID     256
#define GATES   1024   // 4*HID
#define OUTD    128
#define SEQ     512
#define CHUNK   64     // steps per launch (8 launches)

#define CLUSTER   8        // CTAs per cluster (hidden split)
#define NCLUSTER  16       // clusters (batch split)
#define ROWS      16       // batch rows per cluster
#define NLOC      128      // gate cols per CTA (4 gates x 32 hidden cols)
#define JLOC      32       // hidden cols per CTA
#define NTHREADS  512

// smem layout (floats)
#define GPAD   132
#define PARTSZ (ROWS * GPAD)                // 2112
#define SM_W   (HID * NLOC)                 // 32768
#define SM_HT  (HID * ROWS * 2)             // 8192 (h transposed, dup pairs)
#define SMEM_FLOATS (SM_W + SM_HT + 4 * PARTSZ + PARTSZ)
#define SMEM_BYTES  (SMEM_FLOATS * 4)       // 206080

// ---------------- persistent device scratch ----------------
__device__ float g_wT_hh[HID * GATES];   // [k][n]
__device__ float g_wT_ih[HID * GATES];   // [k][n]
__device__ float g_fcwT [LATENT * HID];  // [k][j]
__device__ float g_outT [HID * OUTD];    // [k][o]
__device__ float g_h0   [BATCH * HID];
__device__ float g_c    [BATCH * HID];   // c-state spill between chunks
__device__ float g_xproj[BATCH * GATES];
__device__ float g_hs   [SEQ * BATCH * HID];   // [t][b][j]

// ---------------- packed fp32x2 helpers ----------------
__device__ __forceinline__ void fma2(unsigned long long& d, unsigned long long a,
                                     unsigned long long b) {
    asm("fma.rn.f32x2 %0, %1, %2, %0;" : "+l"(d) : "l"(a), "l"(b));
}
__device__ __forceinline__ float2 upk2(unsigned long long v) {
    float2 r;
    asm("mov.b64 {%0, %1}, %2;" : "=f"(r.x), "=f"(r.y) : "l"(v));
    return r;
}

__device__ __forceinline__ float sigmoid_x(float x) {
    return __frcp_rn(1.f + __expf(-x));
}
__device__ __forceinline__ float tanh_x(float x) {
    return 1.f - 2.f * __frcp_rn(1.f + __expf(2.f * x));
}

// ---------------- fused prep: all 4 weight transposes in one kernel ----------------
__device__ __forceinline__ void do_transpose(const float* __restrict__ src,
                                             float* __restrict__ dst,
                                             int R, int C, int bx, int by, int tid) {
    __shared__ float tile[32][33];
    int tx = tid & 31;
    int ty = tid >> 5;
#pragma unroll
    for (int p = 0; p < 32; p += 8) {
        int r = by * 32 + ty + p, c = bx * 32 + tx;
        if (r < R && c < C) tile[ty + p][tx] = src[r * C + c];
    }
    __syncthreads();
#pragma unroll
    for (int p = 0; p < 32; p += 8) {
        int r = by * 32 + tx, c = bx * 32 + ty + p;
        if (r < R && c < C) dst[c * R + r] = tile[tx][ty + p];
    }
}

// block ranges: [0,256) w_hh, [256,512) w_ih, [512,528) fc_w, [528,560) out_w
__global__ void prep_kernel(const float* __restrict__ w_hh, const float* __restrict__ w_ih,
                            const float* __restrict__ fc_w, const float* __restrict__ out_w) {
    int b = blockIdx.x;
    int tid = threadIdx.x;
    if (b < 256) {
        int t = b;                    // grid (C/32=8, R/32=32) for R=GATES,C=HID
        do_transpose(w_hh, g_wT_hh, GATES, HID, t & 7, t >> 3, tid);
    } else if (b < 512) {
        int t = b - 256;
        do_transpose(w_ih, g_wT_ih, GATES, HID, t & 7, t >> 3, tid);
    } else if (b < 528) {
        int t = b - 512;              // R=HID(256), C=LATENT(64): 2 x 8
        do_transpose(fc_w, g_fcwT, HID, LATENT, t & 1, t >> 1, tid);
    } else {
        int t = b - 528;              // R=OUTD(128), C=HID(256): 8 x 4
        do_transpose(out_w, g_outT, OUTD, HID, t & 7, t >> 3, tid);
    }
}

// ---------------- h0 = z @ fc_w^T + fc_b ----------------
__global__ void h0_kernel(const float* __restrict__ z, const float* __restrict__ fc_b) {
    __shared__ float sh_z[4][LATENT];
    int tid = threadIdx.x;
    int b0 = blockIdx.x * 4;
    {
        int row = tid >> 6, k = tid & 63;
        sh_z[row][k] = z[(b0 + row) * LATENT + k];
    }
    __syncthreads();
    float acc0 = 0.f, acc1 = 0.f, acc2 = 0.f, acc3 = 0.f;
    int j = tid;
#pragma unroll 8
    for (int k = 0; k < LATENT; k++) {
        float w = g_fcwT[k * HID + j];
        acc0 = fmaf(sh_z[0][k], w, acc0);
        acc1 = fmaf(sh_z[1][k], w, acc1);
        acc2 = fmaf(sh_z[2][k], w, acc2);
        acc3 = fmaf(sh_z[3][k], w, acc3);
    }
    float bb = fc_b[j];
    g_h0[(b0 + 0) * HID + j] = acc0 + bb;
    g_h0[(b0 + 1) * HID + j] = acc1 + bb;
    g_h0[(b0 + 2) * HID + j] = acc2 + bb;
    g_h0[(b0 + 3) * HID + j] = acc3 + bb;
}

// ---------------- x_proj = h0 @ w_ih^T + (b_ih + b_hh) ----------------
__global__ void xproj_kernel(const float* __restrict__ b_ih, const float* __restrict__ b_hh) {
    __shared__ float sh_h[32][33];
    __shared__ float sh_w[32][64];
    int tid = threadIdx.x;
    int b0 = blockIdx.x * 32;
    int n0 = blockIdx.y * 64;
    int r  = tid & 31;
    int cg = tid >> 5;
    float acc[8];
#pragma unroll
    for (int i = 0; i < 8; i++) acc[i] = 0.f;

    for (int kc = 0; kc < HID; kc += 32) {
#pragma unroll
        for (int p = 0; p < 4; p++) {
            int e = tid + 256 * p;
            int row = e >> 5, col = e & 31;
            sh_h[row][col] = g_h0[(b0 + row) * HID + kc + col];
        }
#pragma unroll
        for (int p = 0; p < 8; p++) {
            int e = tid + 256 * p;
            int krow = e >> 6, c = e & 63;
            sh_w[krow][c] = g_wT_ih[(kc + krow) * GATES + n0 + c];
        }
        __syncthreads();
#pragma unroll
        for (int kk = 0; kk < 32; kk++) {
            float a = sh_h[r][kk];
            float4 w0 = *reinterpret_cast<const float4*>(&sh_w[kk][cg * 8]);
            float4 w1 = *reinterpret_cast<const float4*>(&sh_w[kk][cg * 8 + 4]);
            acc[0] = fmaf(a, w0.x, acc[0]);
            acc[1] = fmaf(a, w0.y, acc[1]);
            acc[2] = fmaf(a, w0.z, acc[2]);
            acc[3] = fmaf(a, w0.w, acc[3]);
            acc[4] = fmaf(a, w1.x, acc[4]);
            acc[5] = fmaf(a, w1.y, acc[5]);
            acc[6] = fmaf(a, w1.z, acc[6]);
            acc[7] = fmaf(a, w1.w, acc[7]);
        }
        __syncthreads();
    }
#pragma unroll
    for (int i = 0; i < 8; i++) {
        int n = n0 + cg * 8 + i;
        g_xproj[(b0 + r) * GATES + n] = acc[i] + b_ih[n] + b_hh[n];
    }
}

// ---------------- persistent LSTM recurrence (one CHUNK of steps) ----------------
// 16 clusters x 8 CTAs x 512 threads (16 warps -> 4/SMSP for latency hiding).
// Thread = (cg 0..15, rg 0..7, kq 0..3): 2-row x 8-col patch, 64-wide k slice.
// Inner loop: 3x LDS.128 + 8x fma2 per k. 4 k-partials reduced via smem with
// conflict-free layout; fused activations, 1 cell/thread.
__global__ void __launch_bounds__(NTHREADS, 1) __cluster_dims__(CLUSTER, 1, 1)
lstm_persistent_kernel(int t0, int t1) {
    extern __shared__ float smem[];
    float*  sh_w    = smem;                     // [HID][NLOC] permuted
    float2* sh_hT2  = (float2*)(sh_w + SM_W);   // [HID][ROWS] dup pairs
    float*  sh_part = sh_w + SM_W + SM_HT;      // [4][ROWS][GPAD]
    float*  sh_xp   = sh_part + 4 * PARTSZ;     // [ROWS][GPAD]

    const int tid  = threadIdx.x;
    const int rank = blockIdx.x & (CLUSTER - 1);
    const int cl   = blockIdx.x / CLUSTER;
    const int b0   = cl * ROWS;
    const int j0   = rank * JLOC;

    // W_hh slice, permuted: col nl -> (i>>2)*64 + (nl>>3)*4 + (nl&3)
    for (int idx = tid; idx < HID * NLOC; idx += NTHREADS) {
        int k = idx >> 7, nl = idx & 127;
        int g = nl >> 5, jj = nl & 31;
        int c8 = nl >> 3, i = nl & 7;
        int dst = (i >> 2) * 64 + c8 * 4 + (i & 3);
        sh_w[k * NLOC + dst] = g_wT_hh[k * GATES + g * HID + j0 + jj];
    }
    // x_proj slice (n_local layout, padded rows)
    for (int idx = tid; idx < ROWS * NLOC; idx += NTHREADS) {
        int r = idx >> 7, nl = idx & 127;
        int g = nl >> 5, jj = nl & 31;
        sh_xp[r * GPAD + nl] = g_xproj[(b0 + r) * GATES + g * HID + j0 + jj];
    }

    const int cg = tid & 15;          // col group: 8 gate cols
    const int rg = (tid >> 4) & 7;    // row pair: rows 2rg, 2rg+1
    const int kq = tid >> 7;          // k quarter: 64 k values

    // activation assignment: 1 cell per thread (16 rows x 32 cols)
    const int arow = tid >> 5;
    const int aj   = tid & 31;

    float cc;
    if (t0 == 0) cc = 0.f;
    else         cc = g_c[(b0 + arow) * HID + j0 + aj];

    const float*  wrowA = sh_w + (kq * 64) * NLOC + cg * 4;
    const float2* hrow  = sh_hT2 + (kq * 64) * ROWS + rg * 2;

    for (int t = t0; t < t1; t++) {
        const float* hin = t ? (g_hs + (size_t)(t - 1) * BATCH * HID) : g_h0;

        // load our 16 rows of h, transpose + duplicate into [k][row] pairs
        for (int i = tid; i < ROWS * (HID / 4); i += NTHREADS) {   // 2 iters
            int row = i & 15, k4 = i >> 4;
            float4 v = ((const float4*)(hin + (size_t)(b0 + row) * HID))[k4];
            float2* d = sh_hT2 + (k4 * 4) * ROWS + row;
            d[0 * ROWS] = make_float2(v.x, v.x);
            d[1 * ROWS] = make_float2(v.y, v.y);
            d[2 * ROWS] = make_float2(v.z, v.z);
            d[3 * ROWS] = make_float2(v.w, v.w);
        }
        __syncthreads();

        // register-blocked GEMM: 2 rows x 4 col-pairs, 64-wide k slice
        unsigned long long acc[2][4];
#pragma unroll
        for (int r = 0; r < 2; r++)
#pragma unroll
            for (int c = 0; c < 4; c++) acc[r][c] = 0ull;

#pragma unroll 8
        for (int k = 0; k < 64; k++) {
            ulonglong2 h01 = *(const ulonglong2*)(hrow + k * ROWS);  // (h0,h0),(h1,h1)
            const float* wr = wrowA + k * NLOC;
            ulonglong2 wA = *(const ulonglong2*)(wr);        // cols cg*8..+3
            ulonglong2 wB = *(const ulonglong2*)(wr + 64);   // cols cg*8+4..+7
            fma2(acc[0][0], h01.x, wA.x); fma2(acc[0][1], h01.x, wA.y);
            fma2(acc[0][2], h01.x, wB.x); fma2(acc[0][3], h01.x, wB.y);
            fma2(acc[1][0], h01.y, wA.x); fma2(acc[1][1], h01.y, wA.y);
            fma2(acc[1][2], h01.y, wB.x); fma2(acc[1][3], h01.y, wB.y);
        }

        // store k-partials
        {
            float* pb = sh_part + kq * PARTSZ;
#pragma unroll
            for (int r = 0; r < 2; r++) {
                ulonglong2* d = (ulonglong2*)(pb + (rg * 2 + r) * GPAD + cg * 8);
                d[0] = make_ulonglong2(acc[r][0], acc[r][1]);
                d[1] = make_ulonglong2(acc[r][2], acc[r][3]);
            }
        }
        __syncthreads();

        // reduce 4 partials + x_proj, fused activations (1 cell/thread)
        {
            const float* p0 = sh_part + arow * GPAD;
            const float* p1 = p0 + PARTSZ;
            const float* p2 = p1 + PARTSZ;
            const float* p3 = p2 + PARTSZ;
            const float* xr = sh_xp + arow * GPAD;

            float gi = xr[aj]      + ((p0[aj]      + p1[aj])      + (p2[aj]      + p3[aj]));
            float gf = xr[aj + 32] + ((p0[aj + 32] + p1[aj + 32]) + (p2[aj + 32] + p3[aj + 32]));
            float gg = xr[aj + 64] + ((p0[aj + 64] + p1[aj + 64]) + (p2[aj + 64] + p3[aj + 64]));
            float go = xr[aj + 96] + ((p0[aj + 96] + p1[aj + 96]) + (p2[aj + 96] + p3[aj + 96]));

            float iv = sigmoid_x(gi), fv = sigmoid_x(gf);
            float gv = tanh_x(gg),    ov = sigmoid_x(go);
            cc = fv * cc + iv * gv;
            float hh = ov * tanh_x(cc);

            g_hs[(size_t)t * BATCH * HID + (size_t)(b0 + arow) * HID + j0 + aj] = hh;
        }

        // cluster barrier: release our h stores, acquire peers'
        asm volatile("barrier.cluster.arrive.aligned;" ::: "memory");
        asm volatile("barrier.cluster.wait.aligned;" ::: "memory");
    }

    // spill c-state for the next chunk
    g_c[(b0 + arow) * HID + j0 + aj] = cc;
}

// ---------------- output projection (f32x2, dup pairs + permuted W) ----------------
__global__ void out_kernel(const float* __restrict__ out_b, float* __restrict__ out) {
    __shared__ float2 sh_a2[64][17];      // dup (a,a) pairs, padded
    __shared__ float  sh_w[16][128];      // permuted: (i>>2)*64 + c8*4 + (i&3)
    int tid = threadIdx.x;
    int r0 = blockIdx.x * 64;
    int rr = tid & 15;
    int cg = tid >> 4;               // 0..15 -> 8 cols each

    unsigned long long acc[4][4];
#pragma unroll
    for (int q = 0; q < 4; q++)
#pragma unroll
        for (int i = 0; i < 4; i++) acc[q][i] = 0ull;

    for (int kc = 0; kc < HID; kc += 16) {
#pragma unroll
        for (int p = 0; p < 4; p++) {
            int e = tid + 256 * p;
            int row = e >> 4, kk = e & 15;
            float v = g_hs[(size_t)(r0 + row) * HID + kc + kk];
            sh_a2[row][kk] = make_float2(v, v);
        }
#pragma unroll
        for (int p = 0; p < 8; p++) {
            int e = tid + 256 * p;
            int krow = e >> 7, c = e & 127;
            int c8 = c >> 3, i = c & 7;
            sh_w[krow][(i >> 2) * 64 + c8 * 4 + (i & 3)] = g_outT[(kc + krow) * OUTD + c];
        }
        __syncthreads();
#pragma unroll
        for (int kk = 0; kk < 16; kk++) {
            unsigned long long p0 = *(const unsigned long long*)&sh_a2[rr][kk];
            unsigned long long p1 = *(const unsigned long long*)&sh_a2[rr + 16][kk];
            unsigned long long p2 = *(const unsigned long long*)&sh_a2[rr + 32][kk];
            unsigned long long p3 = *(const unsigned long long*)&sh_a2[rr + 48][kk];
            ulonglong2 wA = *(const ulonglong2*)(&sh_w[kk][cg * 4]);
            ulonglong2 wB = *(const ulonglong2*)(&sh_w[kk][64 + cg * 4]);
            fma2(acc[0][0], p0, wA.x); fma2(acc[0][1], p0, wA.y);
            fma2(acc[0][2], p0, wB.x); fma2(acc[0][3], p0, wB.y);
            fma2(acc[1][0], p1, wA.x); fma2(acc[1][1], p1, wA.y);
            fma2(acc[1][2], p1, wB.x); fma2(acc[1][3], p1, wB.y);
            fma2(acc[2][0], p2, wA.x); fma2(acc[2][1], p2, wA.y);
            fma2(acc[2][2], p2, wB.x); fma2(acc[2][3], p2, wB.y);
            fma2(acc[3][0], p3, wA.x); fma2(acc[3][1], p3, wA.y);
            fma2(acc[3][2], p3, wB.x); fma2(acc[3][3], p3, wB.y);
        }
        __syncthreads();
    }

    float ob[8];
#pragma unroll
    for (int i = 0; i < 8; i++) ob[i] = out_b[cg * 8 + i];

#pragma unroll
    for (int q = 0; q < 4; q++) {
        int rIdx = r0 + rr + 16 * q;
        int t = rIdx >> 8;
        int b = rIdx & 255;
        float* dst = out + ((size_t)b * SEQ + t) * OUTD + cg * 8;
#pragma unroll
        for (int i = 0; i < 4; i++) {
            float2 f = upk2(acc[q][i]);
            dst[2 * i]     = f.x + ob[2 * i];
            dst[2 * i + 1] = f.y + ob[2 * i + 1];
        }
    }
}

// ---------------- launch ----------------
extern "C" void kernel_launch(void* const* d_in, const int* in_sizes, int n_in,
                              void* d_out, int out_size) {
    const float* z     = (const float*)d_in[0];
    const float* fc_w  = (const float*)d_in[1];
    const float* fc_b  = (const float*)d_in[2];
    const float* w_ih  = (const float*)d_in[3];
    const float* w_hh  = (const float*)d_in[4];
    const float* b_ih  = (const float*)d_in[5];
    const float* b_hh  = (const float*)d_in[6];
    const float* out_w = (const float*)d_in[7];
    const float* out_b = (const float*)d_in[8];
    float* out = (float*)d_out;

    cudaFuncSetAttribute(lstm_persistent_kernel,
                         cudaFuncAttributeMaxDynamicSharedMemorySize, SMEM_BYTES);

    // launch 0: fused weight reshapes
    prep_kernel<<<560, 256>>>(w_hh, w_ih, fc_w, out_w);
    // launch 1: h0
    h0_kernel<<<BATCH / 4, 256>>>(z, fc_b);
    // launch 2: x_proj
    xproj_kernel<<<dim3(BATCH / 32, GATES / 64), 256>>>(b_ih, b_hh);
    // launches 3..10: the recurrence (8 persistent-cluster chunks of 64 steps)
    for (int c = 0; c < SEQ / CHUNK; c++) {
        lstm_persistent_kernel<<<NCLUSTER * CLUSTER, NTHREADS, SMEM_BYTES>>>(
            c * CHUNK, (c + 1) * CHUNK);
    }
    // launch 11: output projection
    out_kernel<<<(SEQ * BATCH) / 64, 256>>>(out_b, out);
}

// round 11
// speedup vs baseline: 2.4376x; 2.4376x over previous
#include <cuda_runtime.h>
#include <cuda_bf16.h>
#include <math.h>
#include <stdint.h>

#define BATCH   256
#define LATENT  64
#define HID     256
#define GATES   1024
#define OUTD    128
#define SEQ     512
#define CHUNK   64

#define CLUSTER   8
#define NCLUSTER  16
#define ROWS      16
#define JLOC      32
#define NTH       256

#define KPAD 264          // bf16 row stride for h tiles (528B -> 4-bank row shift)

// ---------------- persistent device scratch ----------------
__device__ float g_wT_ih[HID * GATES];
__device__ float g_fcwT [LATENT * HID];
__device__ float g_outT [HID * OUTD];
__device__ float g_h0   [BATCH * HID];
__device__ float g_c    [BATCH * HID];
__device__ float g_xproj[BATCH * GATES];
__device__ float g_hs   [SEQ * BATCH * HID];
__device__ __nv_bfloat16 g_whi[CLUSTER * 128 * 256];   // per-rank [nl][k] row-major
__device__ __nv_bfloat16 g_wlo[CLUSTER * 128 * 256];
__device__ __nv_bfloat16 g_hhi[2][BATCH * HID];        // h split, double-buffered
__device__ __nv_bfloat16 g_hlo[2][BATCH * HID];

// ---------------- helpers ----------------
__device__ __forceinline__ void fma2(unsigned long long& d, unsigned long long a,
                                     unsigned long long b) {
    asm("fma.rn.f32x2 %0, %1, %2, %0;" : "+l"(d) : "l"(a), "l"(b));
}
__device__ __forceinline__ float2 upk2(unsigned long long v) {
    float2 r;
    asm("mov.b64 {%0, %1}, %2;" : "=f"(r.x), "=f"(r.y) : "l"(v));
    return r;
}
__device__ __forceinline__ float sigmoid_x(float x) {
    return __frcp_rn(1.f + __expf(-x));
}
__device__ __forceinline__ float tanh_x(float x) {
    return 1.f - 2.f * __frcp_rn(1.f + __expf(2.f * x));
}
// warp MMA: D[16x8] += A[16x16] * B[16x8], bf16 in, fp32 accum
__device__ __forceinline__ void mma_bf16(float d[4], const uint32_t a[4],
                                         uint32_t b0, uint32_t b1) {
    asm volatile(
        "mma.sync.aligned.m16n8k16.row.col.f32.bf16.bf16.f32 "
        "{%0,%1,%2,%3}, {%4,%5,%6,%7}, {%8,%9}, {%0,%1,%2,%3};"
        : "+f"(d[0]), "+f"(d[1]), "+f"(d[2]), "+f"(d[3])
        : "r"(a[0]), "r"(a[1]), "r"(a[2]), "r"(a[3]), "r"(b0), "r"(b1));
}

// ---------------- prep: W split (bf16 hi/lo) + transposes ----------------
__device__ __forceinline__ void do_transpose(const float* __restrict__ src,
                                             float* __restrict__ dst,
                                             int R, int C, int bx, int by, int tid) {
    __shared__ float tile[32][33];
    int tx = tid & 31;
    int ty = tid >> 5;
#pragma unroll
    for (int p = 0; p < 32; p += 8) {
        int r = by * 32 + ty + p, c = bx * 32 + tx;
        if (r < R && c < C) tile[ty + p][tx] = src[r * C + c];
    }
    __syncthreads();
#pragma unroll
    for (int p = 0; p < 32; p += 8) {
        int r = by * 32 + tx, c = bx * 32 + ty + p;
        if (r < R && c < C) dst[c * R + r] = tile[tx][ty + p];
    }
}

// blocks: [0,256) w_hh split -> g_whi/g_wlo; [256,512) w_ih^T; [512,528) fc_w^T; [528,560) out_w^T
__global__ void prep_kernel(const float* __restrict__ w_hh, const float* __restrict__ w_ih,
                            const float* __restrict__ fc_w, const float* __restrict__ out_w) {
    int b = blockIdx.x;
    int tid = threadIdx.x;
    if (b < 256) {
        int rank = b >> 5, rg = b & 31;
        int k = tid;
#pragma unroll
        for (int q = 0; q < 4; q++) {
            int nl = rg * 4 + q;                 // local gate row: gate*32+jj
            int g = nl >> 5, jj = nl & 31;
            float w = w_hh[(g * 256 + rank * JLOC + jj) * HID + k];
            __nv_bfloat16 hi = __float2bfloat16(w);
            __nv_bfloat16 lo = __float2bfloat16(w - __bfloat162float(hi));
            uint32_t idx = rank * 32768 + nl * 256 + k;
            g_whi[idx] = hi;
            g_wlo[idx] = lo;
        }
    } else if (b < 512) {
        int t = b - 256;
        do_transpose(w_ih, g_wT_ih, GATES, HID, t & 7, t >> 3, tid);
    } else if (b < 528) {
        int t = b - 512;
        do_transpose(fc_w, g_fcwT, HID, LATENT, t & 1, t >> 1, tid);
    } else {
        int t = b - 528;
        do_transpose(out_w, g_outT, OUTD, HID, t & 7, t >> 3, tid);
    }
}

// ---------------- h0 = z @ fc_w^T + fc_b (+ bf16 split into buffer 1) ----------------
__global__ void h0_kernel(const float* __restrict__ z, const float* __restrict__ fc_b) {
    __shared__ float sh_z[4][LATENT];
    int tid = threadIdx.x;
    int b0 = blockIdx.x * 4;
    {
        int row = tid >> 6, k = tid & 63;
        sh_z[row][k] = z[(b0 + row) * LATENT + k];
    }
    __syncthreads();
    float acc0 = 0.f, acc1 = 0.f, acc2 = 0.f, acc3 = 0.f;
    int j = tid;
#pragma unroll 8
    for (int k = 0; k < LATENT; k++) {
        float w = g_fcwT[k * HID + j];
        acc0 = fmaf(sh_z[0][k], w, acc0);
        acc1 = fmaf(sh_z[1][k], w, acc1);
        acc2 = fmaf(sh_z[2][k], w, acc2);
        acc3 = fmaf(sh_z[3][k], w, acc3);
    }
    float bb = fc_b[j];
    float h[4] = {acc0 + bb, acc1 + bb, acc2 + bb, acc3 + bb};
#pragma unroll
    for (int r = 0; r < 4; r++) {
        int idx = (b0 + r) * HID + j;
        g_h0[idx] = h[r];
        __nv_bfloat16 hi = __float2bfloat16(h[r]);
        __nv_bfloat16 lo = __float2bfloat16(h[r] - __bfloat162float(hi));
        g_hhi[1][idx] = hi;
        g_hlo[1][idx] = lo;
    }
}

// ---------------- x_proj = h0 @ w_ih^T + (b_ih + b_hh) ----------------
__global__ void xproj_kernel(const float* __restrict__ b_ih, const float* __restrict__ b_hh) {
    __shared__ float sh_h[32][33];
    __shared__ float sh_w[32][64];
    int tid = threadIdx.x;
    int b0 = blockIdx.x * 32;
    int n0 = blockIdx.y * 64;
    int r  = tid & 31;
    int cg = tid >> 5;
    float acc[8];
#pragma unroll
    for (int i = 0; i < 8; i++) acc[i] = 0.f;

    for (int kc = 0; kc < HID; kc += 32) {
#pragma unroll
        for (int p = 0; p < 4; p++) {
            int e = tid + 256 * p;
            int row = e >> 5, col = e & 31;
            sh_h[row][col] = g_h0[(b0 + row) * HID + kc + col];
        }
#pragma unroll
        for (int p = 0; p < 8; p++) {
            int e = tid + 256 * p;
            int krow = e >> 6, c = e & 63;
            sh_w[krow][c] = g_wT_ih[(kc + krow) * GATES + n0 + c];
        }
        __syncthreads();
#pragma unroll
        for (int kk = 0; kk < 32; kk++) {
            float a = sh_h[r][kk];
            float4 w0 = *reinterpret_cast<const float4*>(&sh_w[kk][cg * 8]);
            float4 w1 = *reinterpret_cast<const float4*>(&sh_w[kk][cg * 8 + 4]);
            acc[0] = fmaf(a, w0.x, acc[0]);
            acc[1] = fmaf(a, w0.y, acc[1]);
            acc[2] = fmaf(a, w0.z, acc[2]);
            acc[3] = fmaf(a, w0.w, acc[3]);
            acc[4] = fmaf(a, w1.x, acc[4]);
            acc[5] = fmaf(a, w1.y, acc[5]);
            acc[6] = fmaf(a, w1.z, acc[6]);
            acc[7] = fmaf(a, w1.w, acc[7]);
        }
        __syncthreads();
    }
#pragma unroll
    for (int i = 0; i < 8; i++) {
        int n = n0 + cg * 8 + i;
        g_xproj[(b0 + r) * GATES + n] = acc[i] + b_ih[n] + b_hh[n];
    }
}

// ---------------- warp-MMA LSTM recurrence (one CHUNK) ----------------
// 16 clusters x 8 CTAs x 256 threads (8 warps). Per step per CTA:
//   D[128 gate-rows, 16 batch] = sum of 3 bf16 MMAs (hi/lo split), fp32 accum.
// W fragments register-resident (loaded once per chunk); h (B) fragments via
// conflict-free LDS.32 from padded [batch][k] bf16 tiles restaged each step.
__global__ void __launch_bounds__(NTH, 1) __cluster_dims__(CLUSTER, 1, 1)
lstm_mma_kernel(int t0, int t1) {
    __shared__ __align__(16) __nv_bfloat16 sBhi[ROWS][KPAD];
    __shared__ __align__(16) __nv_bfloat16 sBlo[ROWS][KPAD];
    __shared__ float sXp[ROWS][132];
    __shared__ float sGx[128][18];

    const int tid  = threadIdx.x;
    const int wid  = tid >> 5;
    const int lane = tid & 31;
    const int rank = blockIdx.x & (CLUSTER - 1);
    const int cl   = blockIdx.x / CLUSTER;
    const int b0   = cl * ROWS;
    const int j0   = rank * JLOC;

    const int gid = lane >> 2;          // fragment row group
    const int kl  = (lane & 3) * 2;     // fragment k pair

    // ---- load W fragments into registers (once per chunk) ----
    uint32_t wHi[16][4], wLo[16][4];
    {
        const __nv_bfloat16* Wh = g_whi + rank * 32768;   // [128][256]
        const __nv_bfloat16* Wl = g_wlo + rank * 32768;
        const int m0 = wid * 16;
#pragma unroll
        for (int kt = 0; kt < 16; kt++) {
            int k0 = kt * 16 + kl;
            wHi[kt][0] = *(const uint32_t*)&Wh[(m0 + gid) * 256 + k0];
            wHi[kt][1] = *(const uint32_t*)&Wh[(m0 + gid + 8) * 256 + k0];
            wHi[kt][2] = *(const uint32_t*)&Wh[(m0 + gid) * 256 + k0 + 8];
            wHi[kt][3] = *(const uint32_t*)&Wh[(m0 + gid + 8) * 256 + k0 + 8];
            wLo[kt][0] = *(const uint32_t*)&Wl[(m0 + gid) * 256 + k0];
            wLo[kt][1] = *(const uint32_t*)&Wl[(m0 + gid + 8) * 256 + k0];
            wLo[kt][2] = *(const uint32_t*)&Wl[(m0 + gid) * 256 + k0 + 8];
            wLo[kt][3] = *(const uint32_t*)&Wl[(m0 + gid + 8) * 256 + k0 + 8];
        }
    }
    // ---- x_proj slice: [r][nl], nl = gate*32+jj ----
    for (int idx = tid; idx < ROWS * 128; idx += NTH) {
        int r = idx >> 7, nl = idx & 127;
        int g = nl >> 5, jj = nl & 31;
        sXp[r][nl] = g_xproj[(b0 + r) * GATES + g * HID + j0 + jj];
    }

    // activation cells: thread -> (ab, aj0), (ab, aj0+1)
    const int ab  = tid >> 4;
    const int aj0 = (tid & 15) * 2;
    float cA, cB;
    if (t0 == 0) { cA = 0.f; cB = 0.f; }
    else {
        float2 cv = *(const float2*)(g_c + (b0 + ab) * HID + j0 + aj0);
        cA = cv.x; cB = cv.y;
    }

    for (int t = t0; t < t1; t++) {
        // ---- stage h tiles (buffer written at step t-1) ----
        const int rbuf = (t + 1) & 1;
        {
            const __nv_bfloat16* sh = g_hhi[rbuf];
            const __nv_bfloat16* sl = g_hlo[rbuf];
#pragma unroll
            for (int it = 0; it < 2; it++) {
                int ci = tid + NTH * it;           // 0..511
                int r = ci >> 5, c = ci & 31;      // 32 x 16B chunks per row
                size_t go = (size_t)(b0 + r) * HID + c * 8;
                *(uint4*)&sBhi[r][c * 8] = *(const uint4*)(sh + go);
                *(uint4*)&sBlo[r][c * 8] = *(const uint4*)(sl + go);
            }
        }
        __syncthreads();

        // ---- MMA: 16 k-steps x 2 n-tiles x 3 split products ----
        float acc0[4] = {0.f, 0.f, 0.f, 0.f};
        float acc1[4] = {0.f, 0.f, 0.f, 0.f};
        const int n0 = gid;        // batch row (n) for ntile 0
        const int n1 = gid + 8;
#pragma unroll
        for (int kt = 0; kt < 16; kt++) {
            int kc = kt * 16 + kl;
            uint32_t b0hi = *(const uint32_t*)&sBhi[n0][kc];
            uint32_t b1hi = *(const uint32_t*)&sBhi[n0][kc + 8];
            uint32_t b0lo = *(const uint32_t*)&sBlo[n0][kc];
            uint32_t b1lo = *(const uint32_t*)&sBlo[n0][kc + 8];
            mma_bf16(acc0, wHi[kt], b0hi, b1hi);
            mma_bf16(acc0, wHi[kt], b0lo, b1lo);
            mma_bf16(acc0, wLo[kt], b0hi, b1hi);
            uint32_t c0hi = *(const uint32_t*)&sBhi[n1][kc];
            uint32_t c1hi = *(const uint32_t*)&sBhi[n1][kc + 8];
            uint32_t c0lo = *(const uint32_t*)&sBlo[n1][kc];
            uint32_t c1lo = *(const uint32_t*)&sBlo[n1][kc + 8];
            mma_bf16(acc1, wHi[kt], c0hi, c1hi);
            mma_bf16(acc1, wHi[kt], c0lo, c1lo);
            mma_bf16(acc1, wLo[kt], c0hi, c1hi);
        }

        // ---- exchange gates via smem: sGx[nl][b] ----
        {
            const int nl0 = wid * 16 + gid;
            const int bc  = 2 * (lane & 3);
            *(float2*)&sGx[nl0][bc]         = make_float2(acc0[0], acc0[1]);
            *(float2*)&sGx[nl0 + 8][bc]     = make_float2(acc0[2], acc0[3]);
            *(float2*)&sGx[nl0][bc + 8]     = make_float2(acc1[0], acc1[1]);
            *(float2*)&sGx[nl0 + 8][bc + 8] = make_float2(acc1[2], acc1[3]);
        }
        __syncthreads();

        // ---- fused activations (2 cells/thread) ----
        {
            int aj1 = aj0 + 1;
            float gi0 = sGx[aj0][ab]      + sXp[ab][aj0];
            float gf0 = sGx[32 + aj0][ab] + sXp[ab][32 + aj0];
            float gg0 = sGx[64 + aj0][ab] + sXp[ab][64 + aj0];
            float go0 = sGx[96 + aj0][ab] + sXp[ab][96 + aj0];
            float gi1 = sGx[aj1][ab]      + sXp[ab][aj1];
            float gf1 = sGx[32 + aj1][ab] + sXp[ab][32 + aj1];
            float gg1 = sGx[64 + aj1][ab] + sXp[ab][64 + aj1];
            float go1 = sGx[96 + aj1][ab] + sXp[ab][96 + aj1];

            cA = sigmoid_x(gf0) * cA + sigmoid_x(gi0) * tanh_x(gg0);
            float hA = sigmoid_x(go0) * tanh_x(cA);
            cB = sigmoid_x(gf1) * cB + sigmoid_x(gi1) * tanh_x(gg1);
            float hB = sigmoid_x(go1) * tanh_x(cB);

            size_t idx = (size_t)(b0 + ab) * HID + j0 + aj0;
            *(float2*)(g_hs + (size_t)t * BATCH * HID + idx) = make_float2(hA, hB);

            __nv_bfloat16 hiA = __float2bfloat16(hA);
            __nv_bfloat16 loA = __float2bfloat16(hA - __bfloat162float(hiA));
            __nv_bfloat16 hiB = __float2bfloat16(hB);
            __nv_bfloat16 loB = __float2bfloat16(hB - __bfloat162float(hiB));
            *(__nv_bfloat162*)(g_hhi[t & 1] + idx) = __halves2bfloat162(hiA, hiB);
            *(__nv_bfloat162*)(g_hlo[t & 1] + idx) = __halves2bfloat162(loA, loB);
        }

        // ---- step barrier across the cluster (also syncs the CTA) ----
        asm volatile("barrier.cluster.arrive.aligned;" ::: "memory");
        asm volatile("barrier.cluster.wait.aligned;" ::: "memory");
    }

    // spill c-state
    *(float2*)(g_c + (b0 + ab) * HID + j0 + aj0) = make_float2(cA, cB);
}

// ---------------- output projection (f32x2, dup pairs + permuted W) ----------------
__global__ void out_kernel(const float* __restrict__ out_b, float* __restrict__ out) {
    __shared__ float2 sh_a2[64][17];
    __shared__ float  sh_w[16][128];
    int tid = threadIdx.x;
    int r0 = blockIdx.x * 64;
    int rr = tid & 15;
    int cg = tid >> 4;

    unsigned long long acc[4][4];
#pragma unroll
    for (int q = 0; q < 4; q++)
#pragma unroll
        for (int i = 0; i < 4; i++) acc[q][i] = 0ull;

    for (int kc = 0; kc < HID; kc += 16) {
#pragma unroll
        for (int p = 0; p < 4; p++) {
            int e = tid + 256 * p;
            int row = e >> 4, kk = e & 15;
            float v = g_hs[(size_t)(r0 + row) * HID + kc + kk];
            sh_a2[row][kk] = make_float2(v, v);
        }
#pragma unroll
        for (int p = 0; p < 8; p++) {
            int e = tid + 256 * p;
            int krow = e >> 7, c = e & 127;
            int c8 = c >> 3, i = c & 7;
            sh_w[krow][(i >> 2) * 64 + c8 * 4 + (i & 3)] = g_outT[(kc + krow) * OUTD + c];
        }
        __syncthreads();
#pragma unroll
        for (int kk = 0; kk < 16; kk++) {
            unsigned long long p0 = *(const unsigned long long*)&sh_a2[rr][kk];
            unsigned long long p1 = *(const unsigned long long*)&sh_a2[rr + 16][kk];
            unsigned long long p2 = *(const unsigned long long*)&sh_a2[rr + 32][kk];
            unsigned long long p3 = *(const unsigned long long*)&sh_a2[rr + 48][kk];
            ulonglong2 wA = *(const ulonglong2*)(&sh_w[kk][cg * 4]);
            ulonglong2 wB = *(const ulonglong2*)(&sh_w[kk][64 + cg * 4]);
            fma2(acc[0][0], p0, wA.x); fma2(acc[0][1], p0, wA.y);
            fma2(acc[0][2], p0, wB.x); fma2(acc[0][3], p0, wB.y);
            fma2(acc[1][0], p1, wA.x); fma2(acc[1][1], p1, wA.y);
            fma2(acc[1][2], p1, wB.x); fma2(acc[1][3], p1, wB.y);
            fma2(acc[2][0], p2, wA.x); fma2(acc[2][1], p2, wA.y);
            fma2(acc[2][2], p2, wB.x); fma2(acc[2][3], p2, wB.y);
            fma2(acc[3][0], p3, wA.x); fma2(acc[3][1], p3, wA.y);
            fma2(acc[3][2], p3, wB.x); fma2(acc[3][3], p3, wB.y);
        }
        __syncthreads();
    }

    float ob[8];
#pragma unroll
    for (int i = 0; i < 8; i++) ob[i] = out_b[cg * 8 + i];

#pragma unroll
    for (int q = 0; q < 4; q++) {
        int rIdx = r0 + rr + 16 * q;
        int t = rIdx >> 8;
        int b = rIdx & 255;
        float* dst = out + ((size_t)b * SEQ + t) * OUTD + cg * 8;
#pragma unroll
        for (int i = 0; i < 4; i++) {
            float2 f = upk2(acc[q][i]);
            dst[2 * i]     = f.x + ob[2 * i];
            dst[2 * i + 1] = f.y + ob[2 * i + 1];
        }
    }
}

// ---------------- launch ----------------
extern "C" void kernel_launch(void* const* d_in, const int* in_sizes, int n_in,
                              void* d_out, int out_size) {
    const float* z     = (const float*)d_in[0];
    const float* fc_w  = (const float*)d_in[1];
    const float* fc_b  = (const float*)d_in[2];
    const float* w_ih  = (const float*)d_in[3];
    const float* w_hh  = (const float*)d_in[4];
    const float* b_ih  = (const float*)d_in[5];
    const float* b_hh  = (const float*)d_in[6];
    const float* out_w = (const float*)d_in[7];
    const float* out_b = (const float*)d_in[8];
    float* out = (float*)d_out;

    // launch 0: weight prep
    prep_kernel<<<560, 256>>>(w_hh, w_ih, fc_w, out_w);
    // launch 1: h0 (+ bf16 split into buffer 1)
    h0_kernel<<<BATCH / 4, 256>>>(z, fc_b);
    // launch 2: x_proj
    xproj_kernel<<<dim3(BATCH / 32, GATES / 64), 256>>>(b_ih, b_hh);
    // launches 3..10: warp-MMA recurrence, 8 chunks of 64 steps
    for (int c = 0; c < SEQ / CHUNK; c++) {
        lstm_mma_kernel<<<NCLUSTER * CLUSTER, NTH>>>(c * CHUNK, (c + 1) * CHUNK);
    }
    // launch 11: output projection
    out_kernel<<<(SEQ * BATCH) / 64, 256>>>(out_b, out);
}